// round 1
// baseline (speedup 1.0000x reference)
#include <cuda_runtime.h>
#include <math.h>

// Problem dims (compile-time constants, verified against metadata):
//   x: [131072, 256], W1: [256,512], b1: [512], W2: [512,512], b2: [512],
//   W3: [512,128], b3: [128], out: [131072, 128] fp32
constexpr int BATCH = 131072;
constexpr int DIN   = 256;
constexpr int HID   = 512;
constexpr int DOUT  = 128;

// Scratch for intermediate activations (no runtime allocation allowed;
// __device__ globals are the sanctioned workaround). 2 x 268 MB.
__device__ float g_h1[(size_t)BATCH * HID];
__device__ float g_h2[(size_t)BATCH * HID];

// Classic SIMT SGEMM: BM=128, BN=128, BK=8, 256 threads, 8x8 per-thread tile.
// C[M,N] = act(A[M,K] @ W[K,N] + bias[N]) with act = tanh or identity.
// A/C selected either from kernel params or from the device scratch buffers
// (sel: 0 = use param pointer, 1 = g_h1, 2 = g_h2) so the host side never
// needs cudaGetSymbolAddress.
template<bool TANH>
__global__ __launch_bounds__(256)
void sgemm_bias_act(const float* __restrict__ Ap, int aSel,
                    const float* __restrict__ W,
                    const float* __restrict__ bias,
                    float* __restrict__ Cp, int cSel,
                    int N, int K)
{
    const float* A = (aSel == 1) ? g_h1 : (aSel == 2) ? g_h2 : Ap;
    float*       C = (cSel == 1) ? g_h1 : (cSel == 2) ? g_h2 : Cp;

    __shared__ float As[8][128];   // transposed A tile: As[k][m]
    __shared__ float Bs[8][128];   // B tile: Bs[k][n]

    const int t     = threadIdx.x;
    const int mBase = blockIdx.y * 128;
    const int nBase = blockIdx.x * 128;

    // A-tile load mapping: 128 rows x 8 k; each thread loads one float4 along k
    const int aRow = t >> 1;          // 0..127
    const int aK   = (t & 1) * 4;     // 0 or 4
    // B-tile load mapping: 8 k-rows x 128 n; each thread loads one float4 along n
    const int bK   = t >> 5;          // 0..7
    const int bN   = (t & 31) * 4;    // 0..124

    const int ty = t >> 4;            // 0..15
    const int tx = t & 15;            // 0..15
    const int mFrag = ty * 8;
    const int nFrag = tx * 8;

    float acc[8][8];
    #pragma unroll
    for (int i = 0; i < 8; i++)
        #pragma unroll
        for (int j = 0; j < 8; j++) acc[i][j] = 0.0f;

    const float* Aptr = A + (size_t)(mBase + aRow) * K + aK;
    const float* Bptr = W + (size_t)bK * N + nBase + bN;

    for (int k0 = 0; k0 < K; k0 += 8) {
        float4 a4 = *reinterpret_cast<const float4*>(Aptr + k0);
        float4 b4 = *reinterpret_cast<const float4*>(Bptr + (size_t)k0 * N);

        As[aK + 0][aRow] = a4.x;
        As[aK + 1][aRow] = a4.y;
        As[aK + 2][aRow] = a4.z;
        As[aK + 3][aRow] = a4.w;
        *reinterpret_cast<float4*>(&Bs[bK][bN]) = b4;
        __syncthreads();

        #pragma unroll
        for (int kk = 0; kk < 8; kk++) {
            float a[8], b[8];
            *reinterpret_cast<float4*>(&a[0]) = *reinterpret_cast<const float4*>(&As[kk][mFrag]);
            *reinterpret_cast<float4*>(&a[4]) = *reinterpret_cast<const float4*>(&As[kk][mFrag + 4]);
            *reinterpret_cast<float4*>(&b[0]) = *reinterpret_cast<const float4*>(&Bs[kk][nFrag]);
            *reinterpret_cast<float4*>(&b[4]) = *reinterpret_cast<const float4*>(&Bs[kk][nFrag + 4]);
            #pragma unroll
            for (int i = 0; i < 8; i++)
                #pragma unroll
                for (int j = 0; j < 8; j++)
                    acc[i][j] = fmaf(a[i], b[j], acc[i][j]);
        }
        __syncthreads();
    }

    // Epilogue: bias + optional tanh, vectorized stores.
    float bv[8];
    *reinterpret_cast<float4*>(&bv[0]) = *reinterpret_cast<const float4*>(&bias[nBase + nFrag]);
    *reinterpret_cast<float4*>(&bv[4]) = *reinterpret_cast<const float4*>(&bias[nBase + nFrag + 4]);

    #pragma unroll
    for (int i = 0; i < 8; i++) {
        float outv[8];
        #pragma unroll
        for (int j = 0; j < 8; j++) {
            float v = acc[i][j] + bv[j];
            outv[j] = TANH ? tanhf(v) : v;
        }
        float* cp = C + (size_t)(mBase + mFrag + i) * N + nBase + nFrag;
        *reinterpret_cast<float4*>(&cp[0]) = *reinterpret_cast<const float4*>(&outv[0]);
        *reinterpret_cast<float4*>(&cp[4]) = *reinterpret_cast<const float4*>(&outv[4]);
    }
}

extern "C" void kernel_launch(void* const* d_in, const int* in_sizes, int n_in,
                              void* d_out, int out_size)
{
    const float* x  = (const float*)d_in[0];
    const float* W1 = (const float*)d_in[1];
    const float* b1 = (const float*)d_in[2];
    const float* W2 = (const float*)d_in[3];
    const float* b2 = (const float*)d_in[4];
    const float* W3 = (const float*)d_in[5];
    const float* b3 = (const float*)d_in[6];
    float* out = (float*)d_out;

    // The fixed-point iteration y <- y + alpha*tanh(F(x)-y) converges to
    // y = F(x) to within ~4e-7 absolute (stop eps=1e-6, alpha=0.2), far under
    // the 1e-3 rel-err gate, so the output is exactly the MLP forward pass.

    dim3 grid12(HID / 128, BATCH / 128);   // (4, 1024)
    dim3 grid3 (DOUT / 128, BATCH / 128);  // (1, 1024)

    // Layer 1: h1 = tanh(x @ W1 + b1)       [M=131072, N=512, K=256]
    sgemm_bias_act<true ><<<grid12, 256>>>(x,       0, W1, b1, nullptr, 1, HID,  DIN);
    // Layer 2: h2 = tanh(h1 @ W2 + b2)      [M=131072, N=512, K=512]
    sgemm_bias_act<true ><<<grid12, 256>>>(nullptr, 1, W2, b2, nullptr, 2, HID,  HID);
    // Layer 3: out = h2 @ W3 + b3           [M=131072, N=128, K=512]
    sgemm_bias_act<false><<<grid3,  256>>>(nullptr, 2, W3, b3, out,     0, DOUT, HID);
}

// round 3
// speedup vs baseline: 2.4711x; 2.4711x over previous
#include <cuda_runtime.h>
#include <cuda_bf16.h>
#include <math.h>
#include <stdint.h>

// x[131072,256] @ W1[256,512] -> tanh -> @W2[512,512] -> tanh -> @W3[512,128] (+biases).
// Fixed-point loop converges to F(x) within ~4e-7 abs => output == MLP forward.
constexpr int BATCH = 131072;
constexpr int DIN   = 256;
constexpr int HID   = 512;
constexpr int DOUT  = 128;

// ---------- device scratch (static; no runtime allocation allowed) ----------
__device__ __align__(256) __nv_bfloat16 g_xh[(size_t)BATCH * DIN];
__device__ __align__(256) __nv_bfloat16 g_xl[(size_t)BATCH * DIN];
__device__ __align__(256) __nv_bfloat16 g_h1h[(size_t)BATCH * HID];
__device__ __align__(256) __nv_bfloat16 g_h1l[(size_t)BATCH * HID];
__device__ __align__(256) __nv_bfloat16 g_h2h[(size_t)BATCH * HID];
__device__ __align__(256) __nv_bfloat16 g_h2l[(size_t)BATCH * HID];

constexpr size_t W1_OFF = 0;
constexpr size_t W1_SZ  = (size_t)HID * DIN;
constexpr size_t W2_OFF = W1_OFF + W1_SZ;
constexpr size_t W2_SZ  = (size_t)HID * HID;
constexpr size_t W3_OFF = W2_OFF + W2_SZ;
constexpr size_t W3_SZ  = (size_t)DOUT * HID;
__device__ __align__(256) __nv_bfloat16 g_wh[W1_SZ + W2_SZ + W3_SZ];
__device__ __align__(256) __nv_bfloat16 g_wl[W1_SZ + W2_SZ + W3_SZ];

// ---------- small PTX helpers (compute_103-safe: no tcgen05) ----------
__device__ __forceinline__ uint32_t smem_u32(const void* p) {
    uint32_t a;
    asm("{ .reg .u64 t; cvta.to.shared.u64 t, %1; cvt.u32.u64 %0, t; }" : "=r"(a) : "l"(p));
    return a;
}
__device__ __forceinline__ void cp16(uint32_t dst, const void* src) {
    asm volatile("cp.async.cg.shared.global [%0], [%1], 16;" :: "r"(dst), "l"(src));
}
__device__ __forceinline__ void cp_commit() { asm volatile("cp.async.commit_group;"); }
__device__ __forceinline__ void cp_wait1()  { asm volatile("cp.async.wait_group 1;"); }
__device__ __forceinline__ void cp_wait0()  { asm volatile("cp.async.wait_group 0;"); }

__device__ __forceinline__ void ldsm4(uint32_t* r, uint32_t addr) {
    asm volatile("ldmatrix.sync.aligned.m8n8.x4.shared.b16 {%0,%1,%2,%3}, [%4];"
                 : "=r"(r[0]), "=r"(r[1]), "=r"(r[2]), "=r"(r[3]) : "r"(addr));
}
__device__ __forceinline__ void mma16816(float* d, const uint32_t* a, const uint32_t* b) {
    asm volatile("mma.sync.aligned.m16n8k16.row.col.f32.bf16.bf16.f32 "
                 "{%0,%1,%2,%3}, {%4,%5,%6,%7}, {%8,%9}, {%0,%1,%2,%3};"
                 : "+f"(d[0]), "+f"(d[1]), "+f"(d[2]), "+f"(d[3])
                 : "r"(a[0]), "r"(a[1]), "r"(a[2]), "r"(a[3]), "r"(b[0]), "r"(b[1]));
}

// fast accurate tanh: (e-1)/(e+1), e=2^(2x*log2e). abs err ~1e-7.
__device__ __forceinline__ float tanh_fast(float x) {
    float xc = fminf(fmaxf(x, -15.0f), 15.0f);
    float e;
    asm("ex2.approx.f32 %0, %1;" : "=f"(e) : "f"(xc * 2.885390081777927f));
    float r;
    asm("rcp.approx.f32 %0, %1;" : "=f"(r) : "f"(e + 1.0f));
    return (e - 1.0f) * r;
}

// split two floats into bf16 hi pair + lo-residual pair (packed b32)
__device__ __forceinline__ void split2(float v0, float v1, uint32_t& hi, uint32_t& lo) {
    __nv_bfloat16 h0 = __float2bfloat16(v0);
    __nv_bfloat16 h1 = __float2bfloat16(v1);
    __nv_bfloat16 l0 = __float2bfloat16(v0 - __bfloat162float(h0));
    __nv_bfloat16 l1 = __float2bfloat16(v1 - __bfloat162float(h1));
    hi = (uint32_t)__bfloat16_as_ushort(h0) | ((uint32_t)__bfloat16_as_ushort(h1) << 16);
    lo = (uint32_t)__bfloat16_as_ushort(l0) | ((uint32_t)__bfloat16_as_ushort(l1) << 16);
}

// ---------- prep: x fp32 -> bf16 hi/lo ----------
__global__ void prep_x(const float* __restrict__ x) {
    size_t i = ((size_t)blockIdx.x * blockDim.x + threadIdx.x) * 4;
    float4 v = *reinterpret_cast<const float4*>(x + i);
    uint2 hi, lo;
    split2(v.x, v.y, hi.x, lo.x);
    split2(v.z, v.w, hi.y, lo.y);
    *reinterpret_cast<uint2*>(&g_xh[i]) = hi;
    *reinterpret_cast<uint2*>(&g_xl[i]) = lo;
}

// ---------- prep: W[K,N] fp32 -> bf16 hi/lo transposed [N,K] ----------
__global__ void prep_w(const float* __restrict__ W, int K, int N, size_t dstOff) {
    int idx = blockIdx.x * blockDim.x + threadIdx.x;   // idx = n*K + k
    if (idx >= K * N) return;
    int n = idx / K;
    int k = idx - n * K;
    float v = W[(size_t)k * N + n];
    __nv_bfloat16 h = __float2bfloat16(v);
    g_wh[dstOff + idx] = h;
    g_wl[dstOff + idx] = __float2bfloat16(v - __bfloat162float(h));
}

// ---------- main GEMM: 128x128 tile, BK=32, double-buffered cp.async, 3-term split ----------
constexpr int STAGE_BYTES = 32768;            // 4 regions x 8KB
constexpr uint32_t OFF_AH = 0;
constexpr uint32_t OFF_AL = 8192;
constexpr uint32_t OFF_BH = 16384;
constexpr uint32_t OFF_BL = 24576;
constexpr int SMEM_TOTAL = 2 * STAGE_BYTES;   // 64KB

template<bool TANH, bool FP32OUT>
__global__ __launch_bounds__(256, 2)
void gemm_hmma(int aSel, size_t wOff, const float* __restrict__ bias,
               int cSel, float* __restrict__ Cf, int N, int K)
{
    const __nv_bfloat16 *Ah, *Al;
    if      (aSel == 0) { Ah = g_xh;  Al = g_xl;  }
    else if (aSel == 1) { Ah = g_h1h; Al = g_h1l; }
    else                { Ah = g_h2h; Al = g_h2l; }
    __nv_bfloat16 *Ch = nullptr, *Cl = nullptr;
    if      (cSel == 1) { Ch = g_h1h; Cl = g_h1l; }
    else if (cSel == 2) { Ch = g_h2h; Cl = g_h2l; }
    const __nv_bfloat16* Wh = g_wh + wOff;
    const __nv_bfloat16* Wl = g_wl + wOff;

    extern __shared__ char smem[];
    const uint32_t sbase = smem_u32(smem);
    const int tid  = threadIdx.x;
    const int wid  = tid >> 5;
    const int lane = tid & 31;
    const int mBase = blockIdx.y * 128;
    const int nBase = blockIdx.x * 128;
    const int warpM = (wid >> 1) * 32;
    const int warpN = (wid & 1) * 64;
    const int NC = K / 32;

    // load thread mapping: per region 512x16B chunks, 2 per thread
    const int r0 = tid >> 2, j0 = (tid & 3);             // chunk 0
    const int r1 = (tid + 256) >> 2, j1 = (tid & 3);     // chunk 1 (row +64)
    const uint32_t so0 = (uint32_t)r0 * 64 + (((uint32_t)j0 * 16) ^ (((uint32_t)r0 & 6) << 3));
    const uint32_t so1 = (uint32_t)r1 * 64 + (((uint32_t)j1 * 16) ^ (((uint32_t)r1 & 6) << 3));

    auto loadChunk = [&](int kc, int s) {
        uint32_t sb = sbase + s * STAGE_BYTES;
        size_t colOff = (size_t)kc * 32 + j0 * 8;
        const __nv_bfloat16* a0 = Ah + (size_t)(mBase + r0) * K + colOff;
        const __nv_bfloat16* a1 = Ah + (size_t)(mBase + r1) * K + colOff;
        const __nv_bfloat16* l0 = Al + (size_t)(mBase + r0) * K + colOff;
        const __nv_bfloat16* l1 = Al + (size_t)(mBase + r1) * K + colOff;
        const __nv_bfloat16* w0 = Wh + (size_t)(nBase + r0) * K + colOff;
        const __nv_bfloat16* w1 = Wh + (size_t)(nBase + r1) * K + colOff;
        const __nv_bfloat16* v0 = Wl + (size_t)(nBase + r0) * K + colOff;
        const __nv_bfloat16* v1 = Wl + (size_t)(nBase + r1) * K + colOff;
        cp16(sb + OFF_AH + so0, a0);  cp16(sb + OFF_AH + so1, a1);
        cp16(sb + OFF_AL + so0, l0);  cp16(sb + OFF_AL + so1, l1);
        cp16(sb + OFF_BH + so0, w0);  cp16(sb + OFF_BH + so1, w1);
        cp16(sb + OFF_BL + so0, v0);  cp16(sb + OFF_BL + so1, v1);
    };

    float acc[2][8][4];
    #pragma unroll
    for (int i = 0; i < 2; i++)
        #pragma unroll
        for (int j = 0; j < 8; j++)
            #pragma unroll
            for (int q = 0; q < 4; q++) acc[i][j][q] = 0.0f;

    const int lrow = lane & 15, lhi = lane >> 4;

    loadChunk(0, 0);
    cp_commit();

    for (int c = 0; c < NC; c++) {
        if (c + 1 < NC) { loadChunk(c + 1, (c + 1) & 1); cp_commit(); cp_wait1(); }
        else            { cp_wait0(); }
        __syncthreads();

        const uint32_t sb = sbase + (c & 1) * STAGE_BYTES;
        #pragma unroll
        for (int ks = 0; ks < 2; ks++) {
            const uint32_t colb = ks * 32 + lhi * 16;
            uint32_t ah[2][4], al[2][4], bb[8][2];
            #pragma unroll
            for (int i = 0; i < 2; i++) {
                uint32_t row = warpM + i * 16 + lrow;
                uint32_t off = row * 64 + (colb ^ ((row & 6) << 3));
                ldsm4(ah[i], sb + OFF_AH + off);
                ldsm4(al[i], sb + OFF_AL + off);
            }
            #pragma unroll
            for (int p = 0; p < 4; p++) {
                uint32_t row = warpN + p * 16 + lrow;
                uint32_t off = row * 64 + (colb ^ ((row & 6) << 3));
                uint32_t r[4];
                ldsm4(r, sb + OFF_BH + off);
                bb[2 * p][0] = r[0]; bb[2 * p][1] = r[2];
                bb[2 * p + 1][0] = r[1]; bb[2 * p + 1][1] = r[3];
            }
            #pragma unroll
            for (int i = 0; i < 2; i++)
                #pragma unroll
                for (int j = 0; j < 8; j++) mma16816(acc[i][j], ah[i], bb[j]);
            #pragma unroll
            for (int i = 0; i < 2; i++)
                #pragma unroll
                for (int j = 0; j < 8; j++) mma16816(acc[i][j], al[i], bb[j]);
            #pragma unroll
            for (int p = 0; p < 4; p++) {
                uint32_t row = warpN + p * 16 + lrow;
                uint32_t off = row * 64 + (colb ^ ((row & 6) << 3));
                uint32_t r[4];
                ldsm4(r, sb + OFF_BL + off);
                bb[2 * p][0] = r[0]; bb[2 * p][1] = r[2];
                bb[2 * p + 1][0] = r[1]; bb[2 * p + 1][1] = r[3];
            }
            #pragma unroll
            for (int i = 0; i < 2; i++)
                #pragma unroll
                for (int j = 0; j < 8; j++) mma16816(acc[i][j], ah[i], bb[j]);
        }
        __syncthreads();
    }

    // ---------- epilogue ----------
    #pragma unroll
    for (int i = 0; i < 2; i++) {
        const int m0 = mBase + warpM + i * 16 + (lane >> 2);
        #pragma unroll
        for (int j = 0; j < 8; j++) {
            const int n = nBase + warpN + j * 8 + (lane & 3) * 2;
            const float2 bb2 = *reinterpret_cast<const float2*>(&bias[n]);
            float v00 = acc[i][j][0] + bb2.x, v01 = acc[i][j][1] + bb2.y;
            float v10 = acc[i][j][2] + bb2.x, v11 = acc[i][j][3] + bb2.y;
            if (TANH) {
                v00 = tanh_fast(v00); v01 = tanh_fast(v01);
                v10 = tanh_fast(v10); v11 = tanh_fast(v11);
            }
            if (FP32OUT) {
                *reinterpret_cast<float2*>(&Cf[(size_t)m0 * N + n])       = make_float2(v00, v01);
                *reinterpret_cast<float2*>(&Cf[(size_t)(m0 + 8) * N + n]) = make_float2(v10, v11);
            } else {
                uint32_t hi, lo;
                split2(v00, v01, hi, lo);
                *reinterpret_cast<uint32_t*>(&Ch[(size_t)m0 * N + n]) = hi;
                *reinterpret_cast<uint32_t*>(&Cl[(size_t)m0 * N + n]) = lo;
                split2(v10, v11, hi, lo);
                *reinterpret_cast<uint32_t*>(&Ch[(size_t)(m0 + 8) * N + n]) = hi;
                *reinterpret_cast<uint32_t*>(&Cl[(size_t)(m0 + 8) * N + n]) = lo;
            }
        }
    }
}

// ---------- launch ----------
extern "C" void kernel_launch(void* const* d_in, const int* in_sizes, int n_in,
                              void* d_out, int out_size)
{
    const float* x  = (const float*)d_in[0];
    const float* W1 = (const float*)d_in[1];
    const float* b1 = (const float*)d_in[2];
    const float* W2 = (const float*)d_in[3];
    const float* b2 = (const float*)d_in[4];
    const float* W3 = (const float*)d_in[5];
    const float* b3 = (const float*)d_in[6];
    float* out = (float*)d_out;

    prep_x<<<(int)((size_t)BATCH * DIN / 4 / 256), 256>>>(x);
    prep_w<<<(int)((W1_SZ + 255) / 256), 256>>>(W1, DIN, HID, W1_OFF);
    prep_w<<<(int)((W2_SZ + 255) / 256), 256>>>(W2, HID, HID, W2_OFF);
    prep_w<<<(int)((W3_SZ + 255) / 256), 256>>>(W3, HID, DOUT, W3_OFF);

    cudaFuncSetAttribute(gemm_hmma<true,  false>,
                         cudaFuncAttributeMaxDynamicSharedMemorySize, SMEM_TOTAL);
    cudaFuncSetAttribute(gemm_hmma<false, true>,
                         cudaFuncAttributeMaxDynamicSharedMemorySize, SMEM_TOTAL);

    dim3 grid12(HID / 128, BATCH / 128);   // (4, 1024)
    dim3 grid3 (DOUT / 128, BATCH / 128);  // (1, 1024)

    // L1: h1 = tanh(x @ W1 + b1)    K=256
    gemm_hmma<true,  false><<<grid12, 256, SMEM_TOTAL>>>(0, W1_OFF, b1, 1, nullptr, HID, DIN);
    // L2: h2 = tanh(h1 @ W2 + b2)   K=512
    gemm_hmma<true,  false><<<grid12, 256, SMEM_TOTAL>>>(1, W2_OFF, b2, 2, nullptr, HID, HID);
    // L3: out = h2 @ W3 + b3        K=512
    gemm_hmma<false, true ><<<grid3,  256, SMEM_TOTAL>>>(2, W3_OFF, b3, 0, out, DOUT, HID);
}